// round 1
// baseline (speedup 1.0000x reference)
#include <cuda_runtime.h>

// Problem constants (fixed shapes)
#define N_TOK 8192
#define CH    1024
#define KC    9                 // 8 spline bases + identity channel
#define KTOT  (CH * KC)         // 9216

// Scratch (device globals are the allowed scratch mechanism)
__device__ float g_F [N_TOK * (size_t)KTOT];   // 302 MB: packed feature matrix [N, KTOT]
__device__ float g_W1[(size_t)KTOT * CH];      // 37.7 MB: packed weights layer 1 [KTOT, CH]
__device__ float g_W2[(size_t)KTOT * CH];
__device__ float g_X1[N_TOK * (size_t)CH];     // 33.5 MB: layer-1 output

// ---------------------------------------------------------------------------
// Pack weights: Wp[(i*9+k), o] = spline_w[o,i,k] for k<8 ; base_w[o,i] for k==8
// ---------------------------------------------------------------------------
__global__ void pack_w_kernel(const float* __restrict__ base_w,
                              const float* __restrict__ spline_w,
                              int which) {
    float* __restrict__ Wp = (which == 0) ? g_W1 : g_W2;
    int idx = blockIdx.x * blockDim.x + threadIdx.x;
    if (idx >= KTOT * CH) return;
    int o  = idx & (CH - 1);
    int ik = idx >> 10;          // CH = 1024
    int i  = ik / KC;
    int k  = ik - i * KC;
    float v;
    if (k < 8) v = spline_w[((size_t)o * CH + i) * 8 + k];
    else       v = base_w[(size_t)o * CH + i];
    Wp[idx] = v;
}

// ---------------------------------------------------------------------------
// Basis: Cox-de Boor cubic B-splines on the extended uniform grid,
// replicated exactly from the reference. Grid knots are compile-time
// constants, so all divisions constant-fold.
// ---------------------------------------------------------------------------
__global__ void basis_kernel(const float* __restrict__ Xext, int use_x1) {
    const float* __restrict__ X = use_x1 ? g_X1 : Xext;
    int idx = blockIdx.x * blockDim.x + threadIdx.x;
    if (idx >= N_TOK * CH) return;
    float x = X[idx];

    const float lo = -0.2f;
    const float h  = (0.2f - (-0.2f)) / 5.0f;   // same fp32 ops as reference
    float t[12];
#pragma unroll
    for (int m = 0; m < 12; m++) t[m] = (float)(m - 3) * h + lo;

    float b[11];
#pragma unroll
    for (int j = 0; j < 11; j++)
        b[j] = (x >= t[j] && x < t[j + 1]) ? 1.0f : 0.0f;

#pragma unroll
    for (int k = 1; k <= 3; k++) {
#pragma unroll
        for (int j = 0; j < 11 - k; j++) {
            // denominators are compile-time constants -> folded reciprocals
            float invL = 1.0f / (t[j + k]     - t[j]);
            float invR = 1.0f / (t[j + k + 1] - t[j + 1]);
            float left  = (x - t[j])         * invL;
            float right = (t[j + k + 1] - x) * invR;
            b[j] = left * b[j] + right * b[j + 1];
        }
    }

    int n = idx >> 10;           // / CH
    int i = idx & (CH - 1);
    float* dst = g_F + (size_t)n * KTOT + (size_t)i * KC;
#pragma unroll
    for (int k = 0; k < 8; k++) dst[k] = b[k];
    dst[8] = x;                  // identity channel carries base_w GEMM
}

// ---------------------------------------------------------------------------
// SGEMM: C[M,N] = A[M,K] * B[K,N], M=8192, K=9216, N=1024, fp32.
// 128x128 tile, BK=16, 256 threads, 8x8 per thread, double-buffered smem.
// ---------------------------------------------------------------------------
#define BM 128
#define BN 128
#define BK 16

__global__ __launch_bounds__(256) void sgemm_kernel(int layer, float* __restrict__ Cout) {
    const float* __restrict__ A = g_F;
    const float* __restrict__ B = (layer == 0) ? g_W1 : g_W2;
    float* __restrict__ C       = (layer == 0) ? g_X1 : Cout;

    __shared__ float As[2][BK][BM + 4];   // +4 pad: spreads store banks
    __shared__ float Bs[2][BK][BN];

    const int tid = threadIdx.x;
    const int tx  = tid & 15;
    const int ty  = tid >> 4;
    const int m0  = blockIdx.y * BM;
    const int n0  = blockIdx.x * BN;

    float acc[8][8] = {};

    float4 a_pref[2], b_pref[2];

    // prologue: global -> regs for tile 0
#pragma unroll
    for (int l = 0; l < 2; l++) {
        int idx = tid + l * 256;
        int ar = idx >> 2, ac4 = idx & 3;
        a_pref[l] = *reinterpret_cast<const float4*>(
            &A[(size_t)(m0 + ar) * KTOT + (ac4 << 2)]);
        int br = idx >> 5, bc4 = idx & 31;
        b_pref[l] = *reinterpret_cast<const float4*>(
            &B[(size_t)br * CH + n0 + (bc4 << 2)]);
    }
    // regs -> smem buf 0
#pragma unroll
    for (int l = 0; l < 2; l++) {
        int idx = tid + l * 256;
        int ar = idx >> 2, ac4 = idx & 3;
        As[0][ac4 * 4 + 0][ar] = a_pref[l].x;
        As[0][ac4 * 4 + 1][ar] = a_pref[l].y;
        As[0][ac4 * 4 + 2][ar] = a_pref[l].z;
        As[0][ac4 * 4 + 3][ar] = a_pref[l].w;
        int br = idx >> 5, bc4 = idx & 31;
        *reinterpret_cast<float4*>(&Bs[0][br][bc4 << 2]) = b_pref[l];
    }
    __syncthreads();

    const int numTiles = KTOT / BK;   // 576
    int buf = 0;
    for (int t = 0; t < numTiles; ++t) {
        const int kt = (t + 1) * BK;
        if (t + 1 < numTiles) {
#pragma unroll
            for (int l = 0; l < 2; l++) {
                int idx = tid + l * 256;
                int ar = idx >> 2, ac4 = idx & 3;
                a_pref[l] = *reinterpret_cast<const float4*>(
                    &A[(size_t)(m0 + ar) * KTOT + kt + (ac4 << 2)]);
                int br = idx >> 5, bc4 = idx & 31;
                b_pref[l] = *reinterpret_cast<const float4*>(
                    &B[(size_t)(kt + br) * CH + n0 + (bc4 << 2)]);
            }
        }
        // compute on current buffer
#pragma unroll
        for (int k = 0; k < BK; k++) {
            float4 a0 = *reinterpret_cast<const float4*>(&As[buf][k][ty * 8]);
            float4 a1 = *reinterpret_cast<const float4*>(&As[buf][k][ty * 8 + 4]);
            float4 b0 = *reinterpret_cast<const float4*>(&Bs[buf][k][tx * 8]);
            float4 b1 = *reinterpret_cast<const float4*>(&Bs[buf][k][tx * 8 + 4]);
            float av[8] = {a0.x, a0.y, a0.z, a0.w, a1.x, a1.y, a1.z, a1.w};
            float bv[8] = {b0.x, b0.y, b0.z, b0.w, b1.x, b1.y, b1.z, b1.w};
#pragma unroll
            for (int i = 0; i < 8; i++)
#pragma unroll
                for (int j = 0; j < 8; j++)
                    acc[i][j] += av[i] * bv[j];
        }
        if (t + 1 < numTiles) {
            int nb = buf ^ 1;
#pragma unroll
            for (int l = 0; l < 2; l++) {
                int idx = tid + l * 256;
                int ar = idx >> 2, ac4 = idx & 3;
                As[nb][ac4 * 4 + 0][ar] = a_pref[l].x;
                As[nb][ac4 * 4 + 1][ar] = a_pref[l].y;
                As[nb][ac4 * 4 + 2][ar] = a_pref[l].z;
                As[nb][ac4 * 4 + 3][ar] = a_pref[l].w;
                int br = idx >> 5, bc4 = idx & 31;
                *reinterpret_cast<float4*>(&Bs[nb][br][bc4 << 2]) = b_pref[l];
            }
            __syncthreads();
            buf = nb;
        }
    }

    // epilogue
#pragma unroll
    for (int i = 0; i < 8; i++) {
        size_t off = (size_t)(m0 + ty * 8 + i) * CH + n0 + tx * 8;
        float4 r0 = make_float4(acc[i][0], acc[i][1], acc[i][2], acc[i][3]);
        float4 r1 = make_float4(acc[i][4], acc[i][5], acc[i][6], acc[i][7]);
        *reinterpret_cast<float4*>(&C[off])     = r0;
        *reinterpret_cast<float4*>(&C[off + 4]) = r1;
    }
}

// ---------------------------------------------------------------------------
// Launch: pack W1, pack W2, basis(x)->F, GEMM1->X1, basis(X1)->F, GEMM2->out
// ---------------------------------------------------------------------------
extern "C" void kernel_launch(void* const* d_in, const int* in_sizes, int n_in,
                              void* d_out, int out_size) {
    (void)in_sizes; (void)n_in; (void)out_size;
    const float* x   = (const float*)d_in[0];
    const float* bw1 = (const float*)d_in[1];
    const float* sw1 = (const float*)d_in[2];
    const float* bw2 = (const float*)d_in[3];
    const float* sw2 = (const float*)d_in[4];
    float* out = (float*)d_out;

    const int packThreads = 256;
    const int packBlocks  = (KTOT * CH + packThreads - 1) / packThreads;
    pack_w_kernel<<<packBlocks, packThreads>>>(bw1, sw1, 0);
    pack_w_kernel<<<packBlocks, packThreads>>>(bw2, sw2, 1);

    const int basThreads = 256;
    const int basBlocks  = (N_TOK * CH + basThreads - 1) / basThreads;
    dim3 gemmGrid(CH / BN, N_TOK / BM);   // (8, 64)

    basis_kernel<<<basBlocks, basThreads>>>(x, 0);
    sgemm_kernel<<<gemmGrid, 256>>>(0, out);
    basis_kernel<<<basBlocks, basThreads>>>(x, 1);
    sgemm_kernel<<<gemmGrid, 256>>>(1, out);
}

// round 3
// speedup vs baseline: 2.2901x; 2.2901x over previous
#include <cuda_runtime.h>
#include <cuda_bf16.h>
#include <cstdint>

// ---------------------------------------------------------------------------
// Problem constants
// ---------------------------------------------------------------------------
#define N_TOK 8192
#define CH    1024
#define KC    9
#define KTOT  (CH * KC)          // 9216

// GEMM tiling
#define BM 128
#define BN 128
#define BK 32
#define NKT (KTOT / BK)          // 288 k-tiles
#define PITCH 80                 // bytes per 32-elem bf16 row (64 + 16 pad)
#define PLANE (128 * PITCH)      // 10240 B per plane (128 rows)
#define STAGE (4 * PLANE)        // Ahi, Alo, Bhi, Blo
#define NSTAGE 4
#define SMEM_TOTAL (NSTAGE * STAGE)   // 163840

// ---------------------------------------------------------------------------
// Device scratch
// ---------------------------------------------------------------------------
__device__ __nv_bfloat16 g_Fhi[(size_t)N_TOK * KTOT];
__device__ __nv_bfloat16 g_Flo[(size_t)N_TOK * KTOT];
__device__ __nv_bfloat16 g_W1hi[(size_t)CH * KTOT];
__device__ __nv_bfloat16 g_W1lo[(size_t)CH * KTOT];
__device__ __nv_bfloat16 g_W2hi[(size_t)CH * KTOT];
__device__ __nv_bfloat16 g_W2lo[(size_t)CH * KTOT];
__device__ float         g_X1 [(size_t)N_TOK * CH];

// ---------------------------------------------------------------------------
// PTX helpers (all sm_80-baseline — no 'a'-suffix features)
// ---------------------------------------------------------------------------
__device__ __forceinline__ void cp16(uint32_t s, const void* g) {
    asm volatile("cp.async.cg.shared.global [%0], [%1], 16;" :: "r"(s), "l"(g));
}
__device__ __forceinline__ void cp_commit() {
    asm volatile("cp.async.commit_group;" ::: "memory");
}
template <int N> __device__ __forceinline__ void cp_wait() {
    asm volatile("cp.async.wait_group %0;" :: "n"(N) : "memory");
}
__device__ __forceinline__ void ldsm4(uint32_t* r, uint32_t a) {
    asm volatile("ldmatrix.sync.aligned.m8n8.x4.shared.b16 {%0,%1,%2,%3}, [%4];"
                 : "=r"(r[0]), "=r"(r[1]), "=r"(r[2]), "=r"(r[3]) : "r"(a));
}
__device__ __forceinline__ void ldsm2(uint32_t* r, uint32_t a) {
    asm volatile("ldmatrix.sync.aligned.m8n8.x2.shared.b16 {%0,%1}, [%2];"
                 : "=r"(r[0]), "=r"(r[1]) : "r"(a));
}
__device__ __forceinline__ void mma16816(float* c, const uint32_t* a,
                                         const uint32_t* b) {
    asm volatile(
        "mma.sync.aligned.m16n8k16.row.col.f32.bf16.bf16.f32 "
        "{%0,%1,%2,%3}, {%4,%5,%6,%7}, {%8,%9}, {%0,%1,%2,%3};"
        : "+f"(c[0]), "+f"(c[1]), "+f"(c[2]), "+f"(c[3])
        : "r"(a[0]), "r"(a[1]), "r"(a[2]), "r"(a[3]), "r"(b[0]), "r"(b[1]));
}

// ---------------------------------------------------------------------------
// Weight pack: Wt[n][i*9+kk] = kk<8 ? spline_w[n,i,kk] : base_w[n,i], bf16 hi/lo
// ---------------------------------------------------------------------------
__global__ void pack_w_kernel(const float* __restrict__ base_w,
                              const float* __restrict__ spline_w, int which) {
    __nv_bfloat16* __restrict__ Whi = which ? g_W2hi : g_W1hi;
    __nv_bfloat16* __restrict__ Wlo = which ? g_W2lo : g_W1lo;
    size_t idx = (size_t)blockIdx.x * blockDim.x + threadIdx.x;
    if (idx >= (size_t)CH * KTOT) return;
    int n = (int)(idx / KTOT);
    int k = (int)(idx - (size_t)n * KTOT);
    int i = k / KC;
    int kk = k - i * KC;
    float v = (kk < 8) ? spline_w[((size_t)n * CH + i) * 8 + kk]
                       : base_w[(size_t)n * CH + i];
    __nv_bfloat16 hi = __float2bfloat16(v);
    __nv_bfloat16 lo = __float2bfloat16(v - __bfloat162float(hi));
    Whi[idx] = hi;
    Wlo[idx] = lo;
}

// ---------------------------------------------------------------------------
// Basis: Cox-de Boor cubic splines (exact reference arithmetic), bf16 hi/lo out
// ---------------------------------------------------------------------------
__global__ void basis_kernel(const float* __restrict__ Xext, int use_x1) {
    const float* __restrict__ X = use_x1 ? g_X1 : Xext;
    __shared__ __align__(16) __nv_bfloat16 shi[256 * 9];
    __shared__ __align__(16) __nv_bfloat16 slo[256 * 9];

    int n  = blockIdx.y;
    int i0 = blockIdx.x * 256;
    int tid = threadIdx.x;
    float x = X[(size_t)n * CH + i0 + tid];

    const float lo_g = -0.2f;
    const float h    = (0.2f - (-0.2f)) / 5.0f;
    float t[12];
#pragma unroll
    for (int m = 0; m < 12; m++) t[m] = (float)(m - 3) * h + lo_g;

    float b[11];
#pragma unroll
    for (int j = 0; j < 11; j++) b[j] = (x >= t[j] && x < t[j + 1]) ? 1.0f : 0.0f;
#pragma unroll
    for (int k = 1; k <= 3; k++) {
#pragma unroll
        for (int j = 0; j < 11 - k; j++) {
            float invL = 1.0f / (t[j + k] - t[j]);
            float invR = 1.0f / (t[j + k + 1] - t[j + 1]);
            b[j] = (x - t[j]) * invL * b[j] + (t[j + k + 1] - x) * invR * b[j + 1];
        }
    }

    float v9[9];
#pragma unroll
    for (int k = 0; k < 8; k++) v9[k] = b[k];
    v9[8] = x;
#pragma unroll
    for (int k = 0; k < 9; k++) {
        __nv_bfloat16 hi = __float2bfloat16(v9[k]);
        __nv_bfloat16 lo = __float2bfloat16(v9[k] - __bfloat162float(hi));
        shi[tid * 9 + k] = hi;
        slo[tid * 9 + k] = lo;
    }
    __syncthreads();

    size_t base = (size_t)n * KTOT + (size_t)i0 * KC;
    const float4* s4h = reinterpret_cast<const float4*>(shi);
    const float4* s4l = reinterpret_cast<const float4*>(slo);
    float4* dh = reinterpret_cast<float4*>(&g_Fhi[base]);
    float4* dl = reinterpret_cast<float4*>(&g_Flo[base]);
    for (int c = tid; c < 288; c += 256) {
        dh[c] = s4h[c];
        dl[c] = s4l[c];
    }
}

// ---------------------------------------------------------------------------
// GEMM: C[8192,1024] = F * W^T via mma.sync bf16 hi/lo 3-product split.
// CTA 128x128x32, 8 warps (2m x 4n), warp tile 64x32, 4-stage cp.async.
// ---------------------------------------------------------------------------
__device__ __forceinline__ void load_stage(
    uint32_t sbuf, int kt, int m0, int n0, int tid,
    const __nv_bfloat16* __restrict__ Ah, const __nv_bfloat16* __restrict__ Al,
    const __nv_bfloat16* __restrict__ Bh, const __nv_bfloat16* __restrict__ Bl) {
#pragma unroll
    for (int j = 0; j < 2; j++) {
        int c = tid + j * 256;
        int row = c >> 2, col = c & 3;
        uint32_t soff = row * PITCH + col * 16;
        size_t gA = (size_t)(m0 + row) * KTOT + kt * BK + col * 8;
        size_t gB = (size_t)(n0 + row) * KTOT + kt * BK + col * 8;
        cp16(sbuf + soff,             Ah + gA);
        cp16(sbuf + PLANE + soff,     Al + gA);
        cp16(sbuf + 2 * PLANE + soff, Bh + gB);
        cp16(sbuf + 3 * PLANE + soff, Bl + gB);
    }
}

__global__ __launch_bounds__(256) void kan_gemm_kernel(int layer,
                                                       float* __restrict__ Cout) {
    extern __shared__ char smem[];
    uint32_t sb;
    {
        uint64_t tmp;
        asm("cvta.to.shared.u64 %0, %1;" : "=l"(tmp) : "l"(smem));
        sb = (uint32_t)tmp;
    }
    const __nv_bfloat16* __restrict__ Ah = g_Fhi;
    const __nv_bfloat16* __restrict__ Al = g_Flo;
    const __nv_bfloat16* __restrict__ Bh = layer ? g_W2hi : g_W1hi;
    const __nv_bfloat16* __restrict__ Bl = layer ? g_W2lo : g_W1lo;
    float* __restrict__ C = layer ? Cout : g_X1;

    const int tid = threadIdx.x;
    const int lane = tid & 31;
    const int wid = tid >> 5;
    const int warp_m = wid & 1;        // 2 m-slots of 64
    const int warp_n = wid >> 1;       // 4 n-slots of 32
    const int m0 = blockIdx.y * BM;
    const int n0 = blockIdx.x * BN;

    float acc[4][4][4];
#pragma unroll
    for (int i = 0; i < 4; i++)
#pragma unroll
        for (int j = 0; j < 4; j++)
#pragma unroll
            for (int r = 0; r < 4; r++) acc[i][j][r] = 0.0f;

    // prologue: stages 0..2
#pragma unroll
    for (int s = 0; s < 3; s++) {
        load_stage(sb + s * STAGE, s, m0, n0, tid, Ah, Al, Bh, Bl);
        cp_commit();
    }

    // hoisted ldmatrix offsets (within a stage buffer)
    const uint32_t aoff = (warp_m * 64 + (lane & 15)) * PITCH + (lane >> 4) * 16;
    const uint32_t boff = 2 * PLANE +
                          (warp_n * 32 + (lane & 7)) * PITCH + ((lane >> 3) & 1) * 16;

    for (int kt = 0; kt < NKT; kt++) {
        cp_wait<2>();
        __syncthreads();

        // prefetch kt+3 into buffer (kt-1)&3 (freed last iteration)
        int u = kt + 3;
        if (u < NKT)
            load_stage(sb + (u & 3) * STAGE, u, m0, n0, tid, Ah, Al, Bh, Bl);
        cp_commit();

        uint32_t buf = sb + (kt & 3) * STAGE;
#pragma unroll
        for (int ks = 0; ks < 2; ks++) {
            uint32_t ahf[4][4], alf[4][4], bhf[4][2], blf[4][2];
#pragma unroll
            for (int mf = 0; mf < 4; mf++) {
                uint32_t ra = buf + aoff + mf * 16 * PITCH + ks * 32;
                ldsm4(ahf[mf], ra);
                ldsm4(alf[mf], ra + PLANE);
            }
#pragma unroll
            for (int nf = 0; nf < 4; nf++) {
                uint32_t rb = buf + boff + nf * 8 * PITCH + ks * 32;
                ldsm2(bhf[nf], rb);
                ldsm2(blf[nf], rb + PLANE);
            }
#pragma unroll
            for (int mf = 0; mf < 4; mf++)
#pragma unroll
                for (int nf = 0; nf < 4; nf++) {
                    mma16816(acc[mf][nf], ahf[mf], bhf[nf]);
                    mma16816(acc[mf][nf], ahf[mf], blf[nf]);
                    mma16816(acc[mf][nf], alf[mf], bhf[nf]);
                }
        }
    }

    // epilogue: c layout — rows t/4 and t/4+8, cols 2*(t%4)+{0,1}
#pragma unroll
    for (int mf = 0; mf < 4; mf++) {
        int row = m0 + warp_m * 64 + mf * 16 + (lane >> 2);
#pragma unroll
        for (int nf = 0; nf < 4; nf++) {
            int col = n0 + warp_n * 32 + nf * 8 + (lane & 3) * 2;
            float2* p0 = reinterpret_cast<float2*>(&C[(size_t)row * CH + col]);
            float2* p1 = reinterpret_cast<float2*>(&C[(size_t)(row + 8) * CH + col]);
            *p0 = make_float2(acc[mf][nf][0], acc[mf][nf][1]);
            *p1 = make_float2(acc[mf][nf][2], acc[mf][nf][3]);
        }
    }
}

// ---------------------------------------------------------------------------
// Launch
// ---------------------------------------------------------------------------
extern "C" void kernel_launch(void* const* d_in, const int* in_sizes, int n_in,
                              void* d_out, int out_size) {
    (void)in_sizes; (void)n_in; (void)out_size;
    const float* x   = (const float*)d_in[0];
    const float* bw1 = (const float*)d_in[1];
    const float* sw1 = (const float*)d_in[2];
    const float* bw2 = (const float*)d_in[3];
    const float* sw2 = (const float*)d_in[4];
    float* out = (float*)d_out;

    cudaFuncSetAttribute(kan_gemm_kernel,
                         cudaFuncAttributeMaxDynamicSharedMemorySize, SMEM_TOTAL);

    const int packBlocks = (CH * KTOT + 255) / 256;
    pack_w_kernel<<<packBlocks, 256>>>(bw1, sw1, 0);
    pack_w_kernel<<<packBlocks, 256>>>(bw2, sw2, 1);

    dim3 basGrid(CH / 256, N_TOK);
    dim3 gemmGrid(CH / BN, N_TOK / BM);   // (8, 64)

    basis_kernel<<<basGrid, 256>>>(x, 0);
    kan_gemm_kernel<<<gemmGrid, 256, SMEM_TOTAL>>>(0, out);
    basis_kernel<<<basGrid, 256>>>(x, 1);
    kan_gemm_kernel<<<gemmGrid, 256, SMEM_TOTAL>>>(1, out);
}

// round 4
// speedup vs baseline: 3.0755x; 1.3429x over previous
#include <cuda_runtime.h>
#include <cuda_bf16.h>
#include <cstdint>

// ---------------------------------------------------------------------------
// Problem constants
// ---------------------------------------------------------------------------
#define N_TOK 8192
#define CH    1024
#define KC    9
#define KTOT  (CH * KC)          // 9216

// GEMM tiling
#define BM 128
#define BN 128
#define BK 32
#define NKT (KTOT / BK)          // 288 k-tiles
#define PLANE 8192               // 128 rows x 64B (swizzled, no pad)
#define STAGE (4 * PLANE)        // Ahi, Alo, Bhi, Blo = 32 KB
#define NSTAGE 3
#define SMEM_TOTAL (NSTAGE * STAGE)   // 98304 -> 2 CTAs/SM

// ---------------------------------------------------------------------------
// Device scratch
// ---------------------------------------------------------------------------
__device__ __nv_bfloat16 g_Fhi[(size_t)N_TOK * KTOT];
__device__ __nv_bfloat16 g_Flo[(size_t)N_TOK * KTOT];
__device__ __nv_bfloat16 g_W1hi[(size_t)CH * KTOT];
__device__ __nv_bfloat16 g_W1lo[(size_t)CH * KTOT];
__device__ __nv_bfloat16 g_W2hi[(size_t)CH * KTOT];
__device__ __nv_bfloat16 g_W2lo[(size_t)CH * KTOT];
__device__ float         g_X1 [(size_t)N_TOK * CH];

// ---------------------------------------------------------------------------
// PTX helpers (sm_80-baseline only; no 'a'-suffix features)
// ---------------------------------------------------------------------------
__device__ __forceinline__ void cp16(uint32_t s, const void* g) {
    asm volatile("cp.async.cg.shared.global [%0], [%1], 16;" :: "r"(s), "l"(g));
}
__device__ __forceinline__ void cp_commit() {
    asm volatile("cp.async.commit_group;" ::: "memory");
}
template <int N> __device__ __forceinline__ void cp_wait() {
    asm volatile("cp.async.wait_group %0;" :: "n"(N) : "memory");
}
__device__ __forceinline__ void ldsm4(uint32_t* r, uint32_t a) {
    asm volatile("ldmatrix.sync.aligned.m8n8.x4.shared.b16 {%0,%1,%2,%3}, [%4];"
                 : "=r"(r[0]), "=r"(r[1]), "=r"(r[2]), "=r"(r[3]) : "r"(a));
}
__device__ __forceinline__ void mma16816(float* c, const uint32_t* a,
                                         const uint32_t* b) {
    asm volatile(
        "mma.sync.aligned.m16n8k16.row.col.f32.bf16.bf16.f32 "
        "{%0,%1,%2,%3}, {%4,%5,%6,%7}, {%8,%9}, {%0,%1,%2,%3};"
        : "+f"(c[0]), "+f"(c[1]), "+f"(c[2]), "+f"(c[3])
        : "r"(a[0]), "r"(a[1]), "r"(a[2]), "r"(a[3]), "r"(b[0]), "r"(b[1]));
}
// swizzled byte offset within an 8KB plane: row in [0,128), chunk in [0,4)
__device__ __forceinline__ uint32_t sw(uint32_t row, uint32_t chunk) {
    return row * 64u + ((chunk ^ ((row >> 1) & 3u)) << 4);
}

// ---------------------------------------------------------------------------
// Weight pack: Wt[n][i*9+kk] = kk<8 ? spline_w[n,i,kk] : base_w[n,i], bf16 hi/lo
// ---------------------------------------------------------------------------
__global__ void pack_w_kernel(const float* __restrict__ base_w,
                              const float* __restrict__ spline_w, int which) {
    __nv_bfloat16* __restrict__ Whi = which ? g_W2hi : g_W1hi;
    __nv_bfloat16* __restrict__ Wlo = which ? g_W2lo : g_W1lo;
    size_t idx = (size_t)blockIdx.x * blockDim.x + threadIdx.x;
    if (idx >= (size_t)CH * KTOT) return;
    int n = (int)(idx / KTOT);
    int k = (int)(idx - (size_t)n * KTOT);
    int i = k / KC;
    int kk = k - i * KC;
    float v = (kk < 8) ? spline_w[((size_t)n * CH + i) * 8 + kk]
                       : base_w[(size_t)n * CH + i];
    __nv_bfloat16 hi = __float2bfloat16(v);
    __nv_bfloat16 lo = __float2bfloat16(v - __bfloat162float(hi));
    Whi[idx] = hi;
    Wlo[idx] = lo;
}

// ---------------------------------------------------------------------------
// Basis: Cox-de Boor cubic splines (exact reference arithmetic), bf16 hi/lo out
// ---------------------------------------------------------------------------
__global__ void basis_kernel(const float* __restrict__ Xext, int use_x1) {
    const float* __restrict__ X = use_x1 ? g_X1 : Xext;
    __shared__ __align__(16) __nv_bfloat16 shi[256 * 9];
    __shared__ __align__(16) __nv_bfloat16 slo[256 * 9];

    int n  = blockIdx.y;
    int i0 = blockIdx.x * 256;
    int tid = threadIdx.x;
    float x = X[(size_t)n * CH + i0 + tid];

    const float lo_g = -0.2f;
    const float h    = (0.2f - (-0.2f)) / 5.0f;
    float t[12];
#pragma unroll
    for (int m = 0; m < 12; m++) t[m] = (float)(m - 3) * h + lo_g;

    float b[11];
#pragma unroll
    for (int j = 0; j < 11; j++) b[j] = (x >= t[j] && x < t[j + 1]) ? 1.0f : 0.0f;
#pragma unroll
    for (int k = 1; k <= 3; k++) {
#pragma unroll
        for (int j = 0; j < 11 - k; j++) {
            float invL = 1.0f / (t[j + k] - t[j]);
            float invR = 1.0f / (t[j + k + 1] - t[j + 1]);
            b[j] = (x - t[j]) * invL * b[j] + (t[j + k + 1] - x) * invR * b[j + 1];
        }
    }

    float v9[9];
#pragma unroll
    for (int k = 0; k < 8; k++) v9[k] = b[k];
    v9[8] = x;
#pragma unroll
    for (int k = 0; k < 9; k++) {
        __nv_bfloat16 hi = __float2bfloat16(v9[k]);
        __nv_bfloat16 lo = __float2bfloat16(v9[k] - __bfloat162float(hi));
        shi[tid * 9 + k] = hi;
        slo[tid * 9 + k] = lo;
    }
    __syncthreads();

    size_t base = (size_t)n * KTOT + (size_t)i0 * KC;
    const float4* s4h = reinterpret_cast<const float4*>(shi);
    const float4* s4l = reinterpret_cast<const float4*>(slo);
    float4* dh = reinterpret_cast<float4*>(&g_Fhi[base]);
    float4* dl = reinterpret_cast<float4*>(&g_Flo[base]);
    for (int c = tid; c < 288; c += 256) {
        dh[c] = s4h[c];
        dl[c] = s4l[c];
    }
}

// ---------------------------------------------------------------------------
// GEMM: C[8192,1024] = F * W^T via mma.sync bf16 hi/lo 3-product split.
// CTA 128x128x32, 8 warps (2m x 4n), 3-stage cp.async, swizzled 64B rows.
// ---------------------------------------------------------------------------
__device__ __forceinline__ void load_stage(
    uint32_t sbuf, int kt, int m0, int n0, int tid,
    const __nv_bfloat16* __restrict__ Ah, const __nv_bfloat16* __restrict__ Al,
    const __nv_bfloat16* __restrict__ Bh, const __nv_bfloat16* __restrict__ Bl) {
#pragma unroll
    for (int j = 0; j < 2; j++) {
        int c = tid + j * 256;
        uint32_t row = (uint32_t)c >> 2, col = (uint32_t)c & 3;
        uint32_t soff = sw(row, col);
        size_t gA = (size_t)(m0 + row) * KTOT + kt * BK + col * 8;
        size_t gB = (size_t)(n0 + row) * KTOT + kt * BK + col * 8;
        cp16(sbuf + soff,             Ah + gA);
        cp16(sbuf + PLANE + soff,     Al + gA);
        cp16(sbuf + 2 * PLANE + soff, Bh + gB);
        cp16(sbuf + 3 * PLANE + soff, Bl + gB);
    }
}

__global__ __launch_bounds__(256, 2) void kan_gemm_kernel(int layer,
                                                          float* __restrict__ Cout) {
    extern __shared__ char smem[];
    uint32_t sb;
    {
        uint64_t tmp;
        asm("cvta.to.shared.u64 %0, %1;" : "=l"(tmp) : "l"(smem));
        sb = (uint32_t)tmp;
    }
    const __nv_bfloat16* __restrict__ Ah = g_Fhi;
    const __nv_bfloat16* __restrict__ Al = g_Flo;
    const __nv_bfloat16* __restrict__ Bh = layer ? g_W2hi : g_W1hi;
    const __nv_bfloat16* __restrict__ Bl = layer ? g_W2lo : g_W1lo;
    float* __restrict__ C = layer ? Cout : g_X1;

    const int tid = threadIdx.x;
    const int lane = tid & 31;
    const int wid = tid >> 5;
    const int warp_m = wid & 1;        // 2 m-slots of 64
    const int warp_n = wid >> 1;       // 4 n-slots of 32
    const int m0 = blockIdx.y * BM;
    const int n0 = blockIdx.x * BN;

    float acc[4][4][4];
#pragma unroll
    for (int i = 0; i < 4; i++)
#pragma unroll
        for (int j = 0; j < 4; j++)
#pragma unroll
            for (int r = 0; r < 4; r++) acc[i][j][r] = 0.0f;

    // prologue: stages 0..2
#pragma unroll
    for (int s = 0; s < 3; s++) {
        load_stage(sb + s * STAGE, s, m0, n0, tid, Ah, Al, Bh, Bl);
        cp_commit();
    }

    // per-lane ldmatrix row/chunk bases
    const uint32_t arow = warp_m * 64 + (lane & 15);          // + mf*16
    const uint32_t achk = (uint32_t)(lane >> 4);              // + ks*2
    const uint32_t brow = warp_n * 32 + ((lane >> 4) << 3) + (lane & 7); // + nfp*16
    const uint32_t bchk = (uint32_t)((lane >> 3) & 1);        // + ks*2

    for (int kt = 0; kt < NKT; kt++) {
        cp_wait<2>();
        __syncthreads();

        uint32_t buf = sb + (kt % 3) * STAGE;
#pragma unroll
        for (int ks = 0; ks < 2; ks++) {
            uint32_t ahf[4][4], alf[4][4], bhf[4][2], blf[4][2];
#pragma unroll
            for (int mf = 0; mf < 4; mf++) {
                uint32_t ra = buf + sw(arow + mf * 16, achk + ks * 2);
                ldsm4(ahf[mf], ra);
                ldsm4(alf[mf], ra + PLANE);
            }
#pragma unroll
            for (int nfp = 0; nfp < 2; nfp++) {
                uint32_t rb = buf + 2 * PLANE + sw(brow + nfp * 16, bchk + ks * 2);
                uint32_t r4[4];
                ldsm4(r4, rb);
                bhf[nfp * 2][0] = r4[0]; bhf[nfp * 2][1] = r4[1];
                bhf[nfp * 2 + 1][0] = r4[2]; bhf[nfp * 2 + 1][1] = r4[3];
                ldsm4(r4, rb + PLANE);
                blf[nfp * 2][0] = r4[0]; blf[nfp * 2][1] = r4[1];
                blf[nfp * 2 + 1][0] = r4[2]; blf[nfp * 2 + 1][1] = r4[3];
            }
#pragma unroll
            for (int mf = 0; mf < 4; mf++)
#pragma unroll
                for (int nf = 0; nf < 4; nf++) {
                    mma16816(acc[mf][nf], ahf[mf], bhf[nf]);
                    mma16816(acc[mf][nf], ahf[mf], blf[nf]);
                    mma16816(acc[mf][nf], alf[mf], bhf[nf]);
                }
        }
        __syncthreads();   // all warps done reading buf before overwrite

        int u = kt + 3;
        if (u < NKT)
            load_stage(buf, u, m0, n0, tid, Ah, Al, Bh, Bl);
        cp_commit();
    }

    // epilogue
#pragma unroll
    for (int mf = 0; mf < 4; mf++) {
        int row = m0 + warp_m * 64 + mf * 16 + (lane >> 2);
#pragma unroll
        for (int nf = 0; nf < 4; nf++) {
            int col = n0 + warp_n * 32 + nf * 8 + (lane & 3) * 2;
            float2* p0 = reinterpret_cast<float2*>(&C[(size_t)row * CH + col]);
            float2* p1 = reinterpret_cast<float2*>(&C[(size_t)(row + 8) * CH + col]);
            *p0 = make_float2(acc[mf][nf][0], acc[mf][nf][1]);
            *p1 = make_float2(acc[mf][nf][2], acc[mf][nf][3]);
        }
    }
}

// ---------------------------------------------------------------------------
// Launch
// ---------------------------------------------------------------------------
extern "C" void kernel_launch(void* const* d_in, const int* in_sizes, int n_in,
                              void* d_out, int out_size) {
    (void)in_sizes; (void)n_in; (void)out_size;
    const float* x   = (const float*)d_in[0];
    const float* bw1 = (const float*)d_in[1];
    const float* sw1 = (const float*)d_in[2];
    const float* bw2 = (const float*)d_in[3];
    const float* sw2 = (const float*)d_in[4];
    float* out = (float*)d_out;

    cudaFuncSetAttribute(kan_gemm_kernel,
                         cudaFuncAttributeMaxDynamicSharedMemorySize, SMEM_TOTAL);

    const int packBlocks = (CH * KTOT + 255) / 256;
    pack_w_kernel<<<packBlocks, 256>>>(bw1, sw1, 0);
    pack_w_kernel<<<packBlocks, 256>>>(bw2, sw2, 1);

    dim3 basGrid(CH / 256, N_TOK);
    dim3 gemmGrid(CH / BN, N_TOK / BM);   // (8, 64)

    basis_kernel<<<basGrid, 256>>>(x, 0);
    kan_gemm_kernel<<<gemmGrid, 256, SMEM_TOTAL>>>(0, out);
    basis_kernel<<<basGrid, 256>>>(x, 1);
    kan_gemm_kernel<<<gemmGrid, 256, SMEM_TOTAL>>>(1, out);
}

// round 6
// speedup vs baseline: 3.1249x; 1.0161x over previous
#include <cuda_runtime.h>
#include <cuda_bf16.h>
#include <cstdint>

// ---------------------------------------------------------------------------
// Problem constants
// ---------------------------------------------------------------------------
#define N_TOK 8192
#define CH    1024
#define KC    9
#define KTOT  (CH * KC)          // 9216

// GEMM tiling
#define BM 128
#define BN 128
#define BK 32
#define NKT (KTOT / BK)          // 288 k-tiles (divisible by 3)
#define PLANE 8192               // 128 rows x 64B (swizzled, no pad)
#define STAGE (4 * PLANE)        // Ahi, Alo, Bhi, Blo = 32 KB
#define NSTAGE 3
#define SMEM_TOTAL (NSTAGE * STAGE)   // 98304 -> 2 CTAs/SM

// ---------------------------------------------------------------------------
// Device scratch
// ---------------------------------------------------------------------------
__device__ __nv_bfloat16 g_Fhi[(size_t)N_TOK * KTOT];
__device__ __nv_bfloat16 g_Flo[(size_t)N_TOK * KTOT];
__device__ __nv_bfloat16 g_W1hi[(size_t)CH * KTOT];
__device__ __nv_bfloat16 g_W1lo[(size_t)CH * KTOT];
__device__ __nv_bfloat16 g_W2hi[(size_t)CH * KTOT];
__device__ __nv_bfloat16 g_W2lo[(size_t)CH * KTOT];
__device__ float         g_X1 [(size_t)N_TOK * CH];

// ---------------------------------------------------------------------------
// PTX helpers (sm_80-baseline only; no 'a'-suffix features)
// ---------------------------------------------------------------------------
__device__ __forceinline__ void cp16(uint32_t s, const void* g) {
    asm volatile("cp.async.cg.shared.global [%0], [%1], 16;" :: "r"(s), "l"(g));
}
__device__ __forceinline__ void cp_commit() {
    asm volatile("cp.async.commit_group;" ::: "memory");
}
template <int N> __device__ __forceinline__ void cp_wait() {
    asm volatile("cp.async.wait_group %0;" :: "n"(N) : "memory");
}
__device__ __forceinline__ void ldsm4(uint32_t* r, uint32_t a) {
    asm volatile("ldmatrix.sync.aligned.m8n8.x4.shared.b16 {%0,%1,%2,%3}, [%4];"
                 : "=r"(r[0]), "=r"(r[1]), "=r"(r[2]), "=r"(r[3]) : "r"(a));
}
__device__ __forceinline__ void mma16816(float* c, const uint32_t* a,
                                         const uint32_t* b) {
    asm volatile(
        "mma.sync.aligned.m16n8k16.row.col.f32.bf16.bf16.f32 "
        "{%0,%1,%2,%3}, {%4,%5,%6,%7}, {%8,%9}, {%0,%1,%2,%3};"
        : "+f"(c[0]), "+f"(c[1]), "+f"(c[2]), "+f"(c[3])
        : "r"(a[0]), "r"(a[1]), "r"(a[2]), "r"(a[3]), "r"(b[0]), "r"(b[1]));
}
// swizzled byte offset within an 8KB plane: row in [0,128), chunk in [0,4)
__device__ __forceinline__ uint32_t sw(uint32_t row, uint32_t chunk) {
    return row * 64u + ((chunk ^ ((row >> 1) & 3u)) << 4);
}

// ---------------------------------------------------------------------------
// Weight pack: Wt[n][i*9+kk] = kk<8 ? spline_w[n,i,kk] : base_w[n,i], bf16 hi/lo
// ---------------------------------------------------------------------------
__global__ void pack_w_kernel(const float* __restrict__ base_w,
                              const float* __restrict__ spline_w, int which) {
    __nv_bfloat16* __restrict__ Whi = which ? g_W2hi : g_W1hi;
    __nv_bfloat16* __restrict__ Wlo = which ? g_W2lo : g_W1lo;
    size_t idx = (size_t)blockIdx.x * blockDim.x + threadIdx.x;
    if (idx >= (size_t)CH * KTOT) return;
    int n = (int)(idx / KTOT);
    int k = (int)(idx - (size_t)n * KTOT);
    int i = k / KC;
    int kk = k - i * KC;
    float v = (kk < 8) ? spline_w[((size_t)n * CH + i) * 8 + kk]
                       : base_w[(size_t)n * CH + i];
    __nv_bfloat16 hi = __float2bfloat16(v);
    __nv_bfloat16 lo = __float2bfloat16(v - __bfloat162float(hi));
    Whi[idx] = hi;
    Wlo[idx] = lo;
}

// ---------------------------------------------------------------------------
// Basis: Cox-de Boor cubic splines (exact reference arithmetic), bf16 hi/lo out
// ---------------------------------------------------------------------------
__global__ void basis_kernel(const float* __restrict__ Xext, int use_x1) {
    const float* __restrict__ X = use_x1 ? g_X1 : Xext;
    __shared__ __align__(16) __nv_bfloat16 shi[256 * 9];
    __shared__ __align__(16) __nv_bfloat16 slo[256 * 9];

    int n  = blockIdx.y;
    int i0 = blockIdx.x * 256;
    int tid = threadIdx.x;
    float x = X[(size_t)n * CH + i0 + tid];

    const float lo_g = -0.2f;
    const float h    = (0.2f - (-0.2f)) / 5.0f;
    float t[12];
#pragma unroll
    for (int m = 0; m < 12; m++) t[m] = (float)(m - 3) * h + lo_g;

    float b[11];
#pragma unroll
    for (int j = 0; j < 11; j++) b[j] = (x >= t[j] && x < t[j + 1]) ? 1.0f : 0.0f;
#pragma unroll
    for (int k = 1; k <= 3; k++) {
#pragma unroll
        for (int j = 0; j < 11 - k; j++) {
            float invL = 1.0f / (t[j + k] - t[j]);
            float invR = 1.0f / (t[j + k + 1] - t[j + 1]);
            b[j] = (x - t[j]) * invL * b[j] + (t[j + k + 1] - x) * invR * b[j + 1];
        }
    }

    float v9[9];
#pragma unroll
    for (int k = 0; k < 8; k++) v9[k] = b[k];
    v9[8] = x;
#pragma unroll
    for (int k = 0; k < 9; k++) {
        __nv_bfloat16 hi = __float2bfloat16(v9[k]);
        __nv_bfloat16 lo = __float2bfloat16(v9[k] - __bfloat162float(hi));
        shi[tid * 9 + k] = hi;
        slo[tid * 9 + k] = lo;
    }
    __syncthreads();

    size_t base = (size_t)n * KTOT + (size_t)i0 * KC;
    const float4* s4h = reinterpret_cast<const float4*>(shi);
    const float4* s4l = reinterpret_cast<const float4*>(slo);
    float4* dh = reinterpret_cast<float4*>(&g_Fhi[base]);
    float4* dl = reinterpret_cast<float4*>(&g_Flo[base]);
    for (int c = tid; c < 288; c += 256) {
        dh[c] = s4h[c];
        dl[c] = s4l[c];
    }
}

// ---------------------------------------------------------------------------
// GEMM: C[8192,1024] = F * W^T via mma.sync bf16 hi/lo 3-product split.
// CTA 128x128x32, 8 warps (2m x 4n), 3-stage cp.async, swizzled 64B rows.
// One barrier per k-tile; prologue depth 2 -> cp_wait<1> (R5 bug: wait<2>
// with only 2 pending groups was a no-op and raced the loads).
// ---------------------------------------------------------------------------
__device__ __forceinline__ void load_stage(
    uint32_t sbuf, int kt, int m0, int n0, int tid,
    const __nv_bfloat16* __restrict__ Ah, const __nv_bfloat16* __restrict__ Al,
    const __nv_bfloat16* __restrict__ Bh, const __nv_bfloat16* __restrict__ Bl) {
#pragma unroll
    for (int j = 0; j < 2; j++) {
        int c = tid + j * 256;
        uint32_t row = (uint32_t)c >> 2, col = (uint32_t)c & 3;
        uint32_t soff = sw(row, col);
        size_t gA = (size_t)(m0 + row) * KTOT + kt * BK + col * 8;
        size_t gB = (size_t)(n0 + row) * KTOT + kt * BK + col * 8;
        cp16(sbuf + soff,             Ah + gA);
        cp16(sbuf + PLANE + soff,     Al + gA);
        cp16(sbuf + 2 * PLANE + soff, Bh + gB);
        cp16(sbuf + 3 * PLANE + soff, Bl + gB);
    }
}

__global__ __launch_bounds__(256, 2) void kan_gemm_kernel(int layer,
                                                          float* __restrict__ Cout) {
    extern __shared__ char smem[];
    uint32_t sb;
    {
        uint64_t tmp;
        asm("cvta.to.shared.u64 %0, %1;" : "=l"(tmp) : "l"(smem));
        sb = (uint32_t)tmp;
    }
    const __nv_bfloat16* __restrict__ Ah = g_Fhi;
    const __nv_bfloat16* __restrict__ Al = g_Flo;
    const __nv_bfloat16* __restrict__ Bh = layer ? g_W2hi : g_W1hi;
    const __nv_bfloat16* __restrict__ Bl = layer ? g_W2lo : g_W1lo;
    float* __restrict__ C = layer ? Cout : g_X1;

    const int tid = threadIdx.x;
    const int lane = tid & 31;
    const int wid = tid >> 5;
    const int warp_m = wid & 1;        // 2 m-slots of 64
    const int warp_n = wid >> 1;       // 4 n-slots of 32
    const int m0 = blockIdx.y * BM;
    const int n0 = blockIdx.x * BN;

    float acc[4][4][4];
#pragma unroll
    for (int i = 0; i < 4; i++)
#pragma unroll
        for (int j = 0; j < 4; j++)
#pragma unroll
            for (int r = 0; r < 4; r++) acc[i][j][r] = 0.0f;

    // prologue: stages 0 and 1 (2 committed groups -> loop uses cp_wait<1>)
    load_stage(sb, 0, m0, n0, tid, Ah, Al, Bh, Bl);
    cp_commit();
    load_stage(sb + STAGE, 1, m0, n0, tid, Ah, Al, Bh, Bl);
    cp_commit();

    // per-lane ldmatrix row/chunk bases
    const uint32_t arow = warp_m * 64 + (lane & 15);          // + mf*16
    const uint32_t achk = (uint32_t)(lane >> 4);              // + ks*2
    const uint32_t brow = warp_n * 32 + ((lane >> 4) << 3) + (lane & 7); // + nfp*16
    const uint32_t bchk = (uint32_t)((lane >> 3) & 1);        // + ks*2

    for (int kt = 0; kt < NKT; kt += 3) {
#pragma unroll
        for (int s = 0; s < 3; s++) {
            const int k = kt + s;
            // pending = {k, k+1}; wait until <=1 outstanding -> stage k landed
            cp_wait<1>();
            __syncthreads();   // publish stage k; also fences all warps'
                               // iter k-1 reads of buffer (k+2)%3

            // prefetch k+2 into buffer (k+2)%3 (compile-time: (s+2)%3)
            const uint32_t pbuf = sb + ((s + 2) % 3) * STAGE;
            const int u = k + 2;
            if (u < NKT)
                load_stage(pbuf, u, m0, n0, tid, Ah, Al, Bh, Bl);
            cp_commit();

            const uint32_t buf = sb + s * STAGE;
#pragma unroll
            for (int ks = 0; ks < 2; ks++) {
                uint32_t ahf[4][4], alf[4][4], bhf[4][2], blf[4][2];
#pragma unroll
                for (int mf = 0; mf < 4; mf++) {
                    uint32_t ra = buf + sw(arow + mf * 16, achk + ks * 2);
                    ldsm4(ahf[mf], ra);
                    ldsm4(alf[mf], ra + PLANE);
                }
#pragma unroll
                for (int nfp = 0; nfp < 2; nfp++) {
                    uint32_t rb = buf + 2 * PLANE + sw(brow + nfp * 16, bchk + ks * 2);
                    uint32_t r4[4];
                    ldsm4(r4, rb);
                    bhf[nfp * 2][0] = r4[0]; bhf[nfp * 2][1] = r4[1];
                    bhf[nfp * 2 + 1][0] = r4[2]; bhf[nfp * 2 + 1][1] = r4[3];
                    ldsm4(r4, rb + PLANE);
                    blf[nfp * 2][0] = r4[0]; blf[nfp * 2][1] = r4[1];
                    blf[nfp * 2 + 1][0] = r4[2]; blf[nfp * 2 + 1][1] = r4[3];
                }
                // product-major: consecutive MMAs never share an accumulator;
                // per-accumulator order stays hh, hl, lh (same numerics as R4)
#pragma unroll
                for (int mf = 0; mf < 4; mf++)
#pragma unroll
                    for (int nf = 0; nf < 4; nf++)
                        mma16816(acc[mf][nf], ahf[mf], bhf[nf]);
#pragma unroll
                for (int mf = 0; mf < 4; mf++)
#pragma unroll
                    for (int nf = 0; nf < 4; nf++)
                        mma16816(acc[mf][nf], ahf[mf], blf[nf]);
#pragma unroll
                for (int mf = 0; mf < 4; mf++)
#pragma unroll
                    for (int nf = 0; nf < 4; nf++)
                        mma16816(acc[mf][nf], alf[mf], bhf[nf]);
            }
        }
    }

    // epilogue
#pragma unroll
    for (int mf = 0; mf < 4; mf++) {
        int row = m0 + warp_m * 64 + mf * 16 + (lane >> 2);
#pragma unroll
        for (int nf = 0; nf < 4; nf++) {
            int col = n0 + warp_n * 32 + nf * 8 + (lane & 3) * 2;
            float2* p0 = reinterpret_cast<float2*>(&C[(size_t)row * CH + col]);
            float2* p1 = reinterpret_cast<float2*>(&C[(size_t)(row + 8) * CH + col]);
            *p0 = make_float2(acc[mf][nf][0], acc[mf][nf][1]);
            *p1 = make_float2(acc[mf][nf][2], acc[mf][nf][3]);
        }
    }
}

// ---------------------------------------------------------------------------
// Launch
// ---------------------------------------------------------------------------
extern "C" void kernel_launch(void* const* d_in, const int* in_sizes, int n_in,
                              void* d_out, int out_size) {
    (void)in_sizes; (void)n_in; (void)out_size;
    const float* x   = (const float*)d_in[0];
    const float* bw1 = (const float*)d_in[1];
    const float* sw1 = (const float*)d_in[2];
    const float* bw2 = (const float*)d_in[3];
    const float* sw2 = (const float*)d_in[4];
    float* out = (float*)d_out;

    cudaFuncSetAttribute(kan_gemm_kernel,
                         cudaFuncAttributeMaxDynamicSharedMemorySize, SMEM_TOTAL);

    const int packBlocks = (CH * KTOT + 255) / 256;
    pack_w_kernel<<<packBlocks, 256>>>(bw1, sw1, 0);
    pack_w_kernel<<<packBlocks, 256>>>(bw2, sw2, 1);

    dim3 basGrid(CH / 256, N_TOK);
    dim3 gemmGrid(CH / BN, N_TOK / BM);   // (8, 64)

    basis_kernel<<<basGrid, 256>>>(x, 0);
    kan_gemm_kernel<<<gemmGrid, 256, SMEM_TOTAL>>>(0, out);
    basis_kernel<<<basGrid, 256>>>(x, 1);
    kan_gemm_kernel<<<gemmGrid, 256, SMEM_TOTAL>>>(1, out);
}

// round 7
// speedup vs baseline: 4.6551x; 1.4897x over previous
#include <cuda_runtime.h>
#include <cuda_fp16.h>
#include <cstdint>

// ---------------------------------------------------------------------------
// Problem constants
// ---------------------------------------------------------------------------
#define N_TOK 8192
#define CH    1024
#define KC    9
#define KTOT  (CH * KC)          // 9216

// GEMM tiling
#define BM 128
#define BN 128
#define BK 32
#define NKT (KTOT / BK)          // 288 k-tiles (divisible by 4)
#define PLANE 8192               // 128 rows x 64B (swizzled)
#define STAGE (3 * PLANE)        // Ahi, Alo, B = 24 KB
#define NSTAGE 4
#define SMEM_TOTAL (NSTAGE * STAGE)   // 98304 -> 2 CTAs/SM

// ---------------------------------------------------------------------------
// Device scratch
// ---------------------------------------------------------------------------
__device__ __half g_Fhi[(size_t)N_TOK * KTOT];
__device__ __half g_Flo[(size_t)N_TOK * KTOT];
__device__ __half g_W1 [(size_t)CH * KTOT];
__device__ __half g_W2 [(size_t)CH * KTOT];
__device__ float  g_X1 [(size_t)N_TOK * CH];

// ---------------------------------------------------------------------------
// PTX helpers (sm_80-baseline only)
// ---------------------------------------------------------------------------
__device__ __forceinline__ void cp16(uint32_t s, const void* g) {
    asm volatile("cp.async.cg.shared.global [%0], [%1], 16;" :: "r"(s), "l"(g));
}
__device__ __forceinline__ void cp_commit() {
    asm volatile("cp.async.commit_group;" ::: "memory");
}
template <int N> __device__ __forceinline__ void cp_wait() {
    asm volatile("cp.async.wait_group %0;" :: "n"(N) : "memory");
}
__device__ __forceinline__ void ldsm4(uint32_t* r, uint32_t a) {
    asm volatile("ldmatrix.sync.aligned.m8n8.x4.shared.b16 {%0,%1,%2,%3}, [%4];"
                 : "=r"(r[0]), "=r"(r[1]), "=r"(r[2]), "=r"(r[3]) : "r"(a));
}
__device__ __forceinline__ void mma16816(float* c, const uint32_t* a,
                                         const uint32_t* b) {
    asm volatile(
        "mma.sync.aligned.m16n8k16.row.col.f32.f16.f16.f32 "
        "{%0,%1,%2,%3}, {%4,%5,%6,%7}, {%8,%9}, {%0,%1,%2,%3};"
        : "+f"(c[0]), "+f"(c[1]), "+f"(c[2]), "+f"(c[3])
        : "r"(a[0]), "r"(a[1]), "r"(a[2]), "r"(a[3]), "r"(b[0]), "r"(b[1]));
}
// swizzled byte offset within an 8KB plane: row in [0,128), chunk in [0,4)
__device__ __forceinline__ uint32_t sw(uint32_t row, uint32_t chunk) {
    return row * 64u + ((chunk ^ ((row >> 1) & 3u)) << 4);
}

// ---------------------------------------------------------------------------
// Weight pack: W[n][i*9+kk] = kk<8 ? spline_w[n,i,kk] : base_w[n,i], fp16
// ---------------------------------------------------------------------------
__global__ void pack_w_kernel(const float* __restrict__ base_w,
                              const float* __restrict__ spline_w, int which) {
    __half* __restrict__ W = which ? g_W2 : g_W1;
    size_t idx = (size_t)blockIdx.x * blockDim.x + threadIdx.x;
    if (idx >= (size_t)CH * KTOT) return;
    int n = (int)(idx / KTOT);
    int k = (int)(idx - (size_t)n * KTOT);
    int i = k / KC;
    int kk = k - i * KC;
    float v = (kk < 8) ? spline_w[((size_t)n * CH + i) * 8 + kk]
                       : base_w[(size_t)n * CH + i];
    W[idx] = __float2half_rn(v);
}

// ---------------------------------------------------------------------------
// Basis: Cox-de Boor cubic splines (exact reference arithmetic), fp16 hi/lo out
// ---------------------------------------------------------------------------
__global__ void basis_kernel(const float* __restrict__ Xext, int use_x1) {
    const float* __restrict__ X = use_x1 ? g_X1 : Xext;
    __shared__ __align__(16) __half shi[256 * 9];
    __shared__ __align__(16) __half slo[256 * 9];

    int n  = blockIdx.y;
    int i0 = blockIdx.x * 256;
    int tid = threadIdx.x;
    float x = X[(size_t)n * CH + i0 + tid];

    const float lo_g = -0.2f;
    const float h    = (0.2f - (-0.2f)) / 5.0f;
    float t[12];
#pragma unroll
    for (int m = 0; m < 12; m++) t[m] = (float)(m - 3) * h + lo_g;

    float b[11];
#pragma unroll
    for (int j = 0; j < 11; j++) b[j] = (x >= t[j] && x < t[j + 1]) ? 1.0f : 0.0f;
#pragma unroll
    for (int k = 1; k <= 3; k++) {
#pragma unroll
        for (int j = 0; j < 11 - k; j++) {
            float invL = 1.0f / (t[j + k] - t[j]);
            float invR = 1.0f / (t[j + k + 1] - t[j + 1]);
            b[j] = (x - t[j]) * invL * b[j] + (t[j + k + 1] - x) * invR * b[j + 1];
        }
    }

    float v9[9];
#pragma unroll
    for (int k = 0; k < 8; k++) v9[k] = b[k];
    v9[8] = x;
#pragma unroll
    for (int k = 0; k < 9; k++) {
        __half hi = __float2half_rn(v9[k]);
        __half lo = __float2half_rn(v9[k] - __half2float(hi));
        shi[tid * 9 + k] = hi;
        slo[tid * 9 + k] = lo;
    }
    __syncthreads();

    size_t base = (size_t)n * KTOT + (size_t)i0 * KC;
    const float4* s4h = reinterpret_cast<const float4*>(shi);
    const float4* s4l = reinterpret_cast<const float4*>(slo);
    float4* dh = reinterpret_cast<float4*>(&g_Fhi[base]);
    float4* dl = reinterpret_cast<float4*>(&g_Flo[base]);
    for (int c = tid; c < 288; c += 256) {
        dh[c] = s4h[c];
        dl[c] = s4l[c];
    }
}

// ---------------------------------------------------------------------------
// GEMM: C = F * W^T, fp16 2-product split (A_hi*B + A_lo*B), fp32 accum.
// CTA 128x128x32, 8 warps (2m x 4n), 4-stage cp.async, swizzled 64B rows.
// ---------------------------------------------------------------------------
__device__ __forceinline__ void load_stage(
    uint32_t sbuf, int kt, int m0, int n0, int tid,
    const __half* __restrict__ Ah, const __half* __restrict__ Al,
    const __half* __restrict__ B) {
#pragma unroll
    for (int j = 0; j < 2; j++) {
        int c = tid + j * 256;
        uint32_t row = (uint32_t)c >> 2, col = (uint32_t)c & 3;
        uint32_t soff = sw(row, col);
        size_t gA = (size_t)(m0 + row) * KTOT + kt * BK + col * 8;
        size_t gB = (size_t)(n0 + row) * KTOT + kt * BK + col * 8;
        cp16(sbuf + soff,             Ah + gA);
        cp16(sbuf + PLANE + soff,     Al + gA);
        cp16(sbuf + 2 * PLANE + soff, B + gB);
    }
}

__global__ __launch_bounds__(256, 2) void kan_gemm_kernel(int layer,
                                                          float* __restrict__ Cout) {
    extern __shared__ char smem[];
    uint32_t sb;
    {
        uint64_t tmp;
        asm("cvta.to.shared.u64 %0, %1;" : "=l"(tmp) : "l"(smem));
        sb = (uint32_t)tmp;
    }
    const __half* __restrict__ Ah = g_Fhi;
    const __half* __restrict__ Al = g_Flo;
    const __half* __restrict__ B  = layer ? g_W2 : g_W1;
    float* __restrict__ C = layer ? Cout : g_X1;

    const int tid = threadIdx.x;
    const int lane = tid & 31;
    const int wid = tid >> 5;
    const int warp_m = wid & 1;        // 2 m-slots of 64
    const int warp_n = wid >> 1;       // 4 n-slots of 32
    const int m0 = blockIdx.y * BM;
    const int n0 = blockIdx.x * BN;

    float acc[4][4][4];
#pragma unroll
    for (int i = 0; i < 4; i++)
#pragma unroll
        for (int j = 0; j < 4; j++)
#pragma unroll
            for (int r = 0; r < 4; r++) acc[i][j][r] = 0.0f;

    // prologue: stages 0..2 (3 committed groups -> loop uses cp_wait<2>)
#pragma unroll
    for (int s = 0; s < 3; s++) {
        load_stage(sb + s * STAGE, s, m0, n0, tid, Ah, Al, B);
        cp_commit();
    }

    // per-lane ldmatrix row/chunk bases
    const uint32_t arow = warp_m * 64 + (lane & 15);          // + mf*16
    const uint32_t achk = (uint32_t)(lane >> 4);              // + ks*2
    const uint32_t brow = warp_n * 32 + ((lane >> 4) << 3) + (lane & 7); // + nfp*16
    const uint32_t bchk = (uint32_t)((lane >> 3) & 1);        // + ks*2

    for (int kt = 0; kt < NKT; kt += 4) {
#pragma unroll
        for (int s = 0; s < 4; s++) {
            const int k = kt + s;
            // pending = {k, k+1, k+2}; wait until <=2 -> stage k landed
            cp_wait<2>();
            __syncthreads();   // publish stage k; fences iter k-1 reads of
                               // buffer (k+3)%4

            // prefetch k+3 into buffer (k+3)%4 (compile-time: (s+3)&3)
            const uint32_t pbuf = sb + ((s + 3) & 3) * STAGE;
            const int u = k + 3;
            if (u < NKT)
                load_stage(pbuf, u, m0, n0, tid, Ah, Al, B);
            cp_commit();

            const uint32_t buf = sb + s * STAGE;
#pragma unroll
            for (int ks = 0; ks < 2; ks++) {
                uint32_t ahf[4][4], alf[4][4], bf[4][2];
#pragma unroll
                for (int mf = 0; mf < 4; mf++) {
                    uint32_t ra = buf + sw(arow + mf * 16, achk + ks * 2);
                    ldsm4(ahf[mf], ra);
                    ldsm4(alf[mf], ra + PLANE);
                }
#pragma unroll
                for (int nfp = 0; nfp < 2; nfp++) {
                    uint32_t rb = buf + 2 * PLANE + sw(brow + nfp * 16, bchk + ks * 2);
                    uint32_t r4[4];
                    ldsm4(r4, rb);
                    bf[nfp * 2][0] = r4[0]; bf[nfp * 2][1] = r4[1];
                    bf[nfp * 2 + 1][0] = r4[2]; bf[nfp * 2 + 1][1] = r4[3];
                }
                // product-major: hi product sweep, then lo product sweep
#pragma unroll
                for (int mf = 0; mf < 4; mf++)
#pragma unroll
                    for (int nf = 0; nf < 4; nf++)
                        mma16816(acc[mf][nf], ahf[mf], bf[nf]);
#pragma unroll
                for (int mf = 0; mf < 4; mf++)
#pragma unroll
                    for (int nf = 0; nf < 4; nf++)
                        mma16816(acc[mf][nf], alf[mf], bf[nf]);
            }
        }
    }

    // epilogue
#pragma unroll
    for (int mf = 0; mf < 4; mf++) {
        int row = m0 + warp_m * 64 + mf * 16 + (lane >> 2);
#pragma unroll
        for (int nf = 0; nf < 4; nf++) {
            int col = n0 + warp_n * 32 + nf * 8 + (lane & 3) * 2;
            float2* p0 = reinterpret_cast<float2*>(&C[(size_t)row * CH + col]);
            float2* p1 = reinterpret_cast<float2*>(&C[(size_t)(row + 8) * CH + col]);
            *p0 = make_float2(acc[mf][nf][0], acc[mf][nf][1]);
            *p1 = make_float2(acc[mf][nf][2], acc[mf][nf][3]);
        }
    }
}

// ---------------------------------------------------------------------------
// Launch
// ---------------------------------------------------------------------------
extern "C" void kernel_launch(void* const* d_in, const int* in_sizes, int n_in,
                              void* d_out, int out_size) {
    (void)in_sizes; (void)n_in; (void)out_size;
    const float* x   = (const float*)d_in[0];
    const float* bw1 = (const float*)d_in[1];
    const float* sw1 = (const float*)d_in[2];
    const float* bw2 = (const float*)d_in[3];
    const float* sw2 = (const float*)d_in[4];
    float* out = (float*)d_out;

    cudaFuncSetAttribute(kan_gemm_kernel,
                         cudaFuncAttributeMaxDynamicSharedMemorySize, SMEM_TOTAL);

    const int packBlocks = (CH * KTOT + 255) / 256;
    pack_w_kernel<<<packBlocks, 256>>>(bw1, sw1, 0);
    pack_w_kernel<<<packBlocks, 256>>>(bw2, sw2, 1);

    dim3 basGrid(CH / 256, N_TOK);
    dim3 gemmGrid(CH / BN, N_TOK / BM);   // (8, 64)

    basis_kernel<<<basGrid, 256>>>(x, 0);
    kan_gemm_kernel<<<gemmGrid, 256, SMEM_TOTAL>>>(0, out);
    basis_kernel<<<basGrid, 256>>>(x, 1);
    kan_gemm_kernel<<<gemmGrid, 256, SMEM_TOTAL>>>(1, out);
}

// round 8
// speedup vs baseline: 7.9985x; 1.7182x over previous
#include <cuda_runtime.h>
#include <cuda_fp16.h>
#include <cstdint>

// ---------------------------------------------------------------------------
// Problem constants
// ---------------------------------------------------------------------------
#define N_TOK 8192
#define CH    1024
#define KC    9
#define KTOT  (CH * KC)          // 9216

// GEMM tiling
#define BM 128
#define BN 128
#define BK 32
#define NKT (KTOT / BK)          // 288 k-tiles (divisible by 4)
#define PLANE 8192               // 128 rows x 64B (swizzled)
#define STAGE (2 * PLANE)        // A, B = 16 KB
#define NSTAGE 4
#define SMEM_TOTAL (NSTAGE * STAGE)   // 65536 -> 2 CTAs/SM

// ---------------------------------------------------------------------------
// Device scratch
// ---------------------------------------------------------------------------
__device__ __half g_F  [(size_t)N_TOK * KTOT];
__device__ __half g_W1 [(size_t)CH * KTOT];
__device__ __half g_W2 [(size_t)CH * KTOT];
__device__ float  g_X1 [(size_t)N_TOK * CH];

// ---------------------------------------------------------------------------
// PTX helpers (sm_80-baseline only)
// ---------------------------------------------------------------------------
__device__ __forceinline__ void cp16(uint32_t s, const void* g) {
    asm volatile("cp.async.cg.shared.global [%0], [%1], 16;" :: "r"(s), "l"(g));
}
__device__ __forceinline__ void cp_commit() {
    asm volatile("cp.async.commit_group;" ::: "memory");
}
template <int N> __device__ __forceinline__ void cp_wait() {
    asm volatile("cp.async.wait_group %0;" :: "n"(N) : "memory");
}
__device__ __forceinline__ void ldsm4(uint32_t* r, uint32_t a) {
    asm volatile("ldmatrix.sync.aligned.m8n8.x4.shared.b16 {%0,%1,%2,%3}, [%4];"
                 : "=r"(r[0]), "=r"(r[1]), "=r"(r[2]), "=r"(r[3]) : "r"(a));
}
__device__ __forceinline__ void mma16816(float* c, const uint32_t* a,
                                         const uint32_t* b) {
    asm volatile(
        "mma.sync.aligned.m16n8k16.row.col.f32.f16.f16.f32 "
        "{%0,%1,%2,%3}, {%4,%5,%6,%7}, {%8,%9}, {%0,%1,%2,%3};"
        : "+f"(c[0]), "+f"(c[1]), "+f"(c[2]), "+f"(c[3])
        : "r"(a[0]), "r"(a[1]), "r"(a[2]), "r"(a[3]), "r"(b[0]), "r"(b[1]));
}
// swizzled byte offset within an 8KB plane: row in [0,128), chunk in [0,4)
__device__ __forceinline__ uint32_t sw(uint32_t row, uint32_t chunk) {
    return row * 64u + ((chunk ^ ((row >> 1) & 3u)) << 4);
}

// ---------------------------------------------------------------------------
// Weight pack: W[n][i*9+kk] = kk<8 ? spline_w[n,i,kk] : base_w[n,i], fp16
// ---------------------------------------------------------------------------
__global__ void pack_w_kernel(const float* __restrict__ base_w,
                              const float* __restrict__ spline_w, int which) {
    __half* __restrict__ W = which ? g_W2 : g_W1;
    size_t idx = (size_t)blockIdx.x * blockDim.x + threadIdx.x;
    if (idx >= (size_t)CH * KTOT) return;
    int n = (int)(idx / KTOT);
    int k = (int)(idx - (size_t)n * KTOT);
    int i = k / KC;
    int kk = k - i * KC;
    float v = (kk < 8) ? spline_w[((size_t)n * CH + i) * 8 + kk]
                       : base_w[(size_t)n * CH + i];
    W[idx] = __float2half_rn(v);
}

// ---------------------------------------------------------------------------
// Basis: Cox-de Boor cubic splines (exact reference arithmetic), fp16 out
// ---------------------------------------------------------------------------
__global__ void basis_kernel(const float* __restrict__ Xext, int use_x1) {
    const float* __restrict__ X = use_x1 ? g_X1 : Xext;
    __shared__ __align__(16) __half sv[256 * 9];

    int n  = blockIdx.y;
    int i0 = blockIdx.x * 256;
    int tid = threadIdx.x;
    float x = X[(size_t)n * CH + i0 + tid];

    const float lo_g = -0.2f;
    const float h    = (0.2f - (-0.2f)) / 5.0f;
    float t[12];
#pragma unroll
    for (int m = 0; m < 12; m++) t[m] = (float)(m - 3) * h + lo_g;

    float b[11];
#pragma unroll
    for (int j = 0; j < 11; j++) b[j] = (x >= t[j] && x < t[j + 1]) ? 1.0f : 0.0f;
#pragma unroll
    for (int k = 1; k <= 3; k++) {
#pragma unroll
        for (int j = 0; j < 11 - k; j++) {
            float invL = 1.0f / (t[j + k] - t[j]);
            float invR = 1.0f / (t[j + k + 1] - t[j + 1]);
            b[j] = (x - t[j]) * invL * b[j] + (t[j + k + 1] - x) * invR * b[j + 1];
        }
    }

#pragma unroll
    for (int k = 0; k < 8; k++) sv[tid * 9 + k] = __float2half_rn(b[k]);
    sv[tid * 9 + 8] = __float2half_rn(x);
    __syncthreads();

    size_t base = (size_t)n * KTOT + (size_t)i0 * KC;
    const float4* s4 = reinterpret_cast<const float4*>(sv);
    float4* d4 = reinterpret_cast<float4*>(&g_F[base]);
    for (int c = tid; c < 288; c += 256) d4[c] = s4[c];
}

// ---------------------------------------------------------------------------
// GEMM: C = F * W^T, plain fp16 HMMA, fp32 accum.
// CTA 128x128x32, 8 warps (2m x 4n), 4-stage cp.async, swizzled 64B rows.
// ---------------------------------------------------------------------------
__device__ __forceinline__ void load_stage(
    uint32_t sbuf, int kt, int m0, int n0, int tid,
    const __half* __restrict__ A, const __half* __restrict__ B) {
#pragma unroll
    for (int j = 0; j < 2; j++) {
        int c = tid + j * 256;
        uint32_t row = (uint32_t)c >> 2, col = (uint32_t)c & 3;
        uint32_t soff = sw(row, col);
        size_t gA = (size_t)(m0 + row) * KTOT + kt * BK + col * 8;
        size_t gB = (size_t)(n0 + row) * KTOT + kt * BK + col * 8;
        cp16(sbuf + soff,         A + gA);
        cp16(sbuf + PLANE + soff, B + gB);
    }
}

__global__ __launch_bounds__(256, 2) void kan_gemm_kernel(int layer,
                                                          float* __restrict__ Cout) {
    extern __shared__ char smem[];
    uint32_t sb;
    {
        uint64_t tmp;
        asm("cvta.to.shared.u64 %0, %1;" : "=l"(tmp) : "l"(smem));
        sb = (uint32_t)tmp;
    }
    const __half* __restrict__ A = g_F;
    const __half* __restrict__ B = layer ? g_W2 : g_W1;
    float* __restrict__ C = layer ? Cout : g_X1;

    const int tid = threadIdx.x;
    const int lane = tid & 31;
    const int wid = tid >> 5;
    const int warp_m = wid & 1;        // 2 m-slots of 64
    const int warp_n = wid >> 1;       // 4 n-slots of 32
    const int m0 = blockIdx.y * BM;
    const int n0 = blockIdx.x * BN;

    float acc[4][4][4];
#pragma unroll
    for (int i = 0; i < 4; i++)
#pragma unroll
        for (int j = 0; j < 4; j++)
#pragma unroll
            for (int r = 0; r < 4; r++) acc[i][j][r] = 0.0f;

    // prologue: stages 0..2 (3 committed groups -> loop uses cp_wait<2>)
#pragma unroll
    for (int s = 0; s < 3; s++) {
        load_stage(sb + s * STAGE, s, m0, n0, tid, A, B);
        cp_commit();
    }

    // per-lane ldmatrix row/chunk bases
    const uint32_t arow = warp_m * 64 + (lane & 15);          // + mf*16
    const uint32_t achk = (uint32_t)(lane >> 4);              // + ks*2
    const uint32_t brow = warp_n * 32 + ((lane >> 4) << 3) + (lane & 7); // + nfp*16
    const uint32_t bchk = (uint32_t)((lane >> 3) & 1);        // + ks*2

    for (int kt = 0; kt < NKT; kt += 4) {
#pragma unroll
        for (int s = 0; s < 4; s++) {
            const int k = kt + s;
            // pending = {k, k+1, k+2}; wait until <=2 -> stage k landed
            cp_wait<2>();
            __syncthreads();   // publish stage k; fences iter k-1 reads of
                               // buffer (k+3)%4

            // prefetch k+3 into buffer (k+3)%4 (compile-time: (s+3)&3)
            const uint32_t pbuf = sb + ((s + 3) & 3) * STAGE;
            const int u = k + 3;
            if (u < NKT)
                load_stage(pbuf, u, m0, n0, tid, A, B);
            cp_commit();

            const uint32_t buf = sb + s * STAGE;
#pragma unroll
            for (int ks = 0; ks < 2; ks++) {
                uint32_t af[4][4], bf[4][2];
#pragma unroll
                for (int mf = 0; mf < 4; mf++)
                    ldsm4(af[mf], buf + sw(arow + mf * 16, achk + ks * 2));
#pragma unroll
                for (int nfp = 0; nfp < 2; nfp++) {
                    uint32_t rb = buf + PLANE + sw(brow + nfp * 16, bchk + ks * 2);
                    uint32_t r4[4];
                    ldsm4(r4, rb);
                    bf[nfp * 2][0] = r4[0]; bf[nfp * 2][1] = r4[1];
                    bf[nfp * 2 + 1][0] = r4[2]; bf[nfp * 2 + 1][1] = r4[3];
                }
#pragma unroll
                for (int mf = 0; mf < 4; mf++)
#pragma unroll
                    for (int nf = 0; nf < 4; nf++)
                        mma16816(acc[mf][nf], af[mf], bf[nf]);
            }
        }
    }

    // epilogue
#pragma unroll
    for (int mf = 0; mf < 4; mf++) {
        int row = m0 + warp_m * 64 + mf * 16 + (lane >> 2);
#pragma unroll
        for (int nf = 0; nf < 4; nf++) {
            int col = n0 + warp_n * 32 + nf * 8 + (lane & 3) * 2;
            float2* p0 = reinterpret_cast<float2*>(&C[(size_t)row * CH + col]);
            float2* p1 = reinterpret_cast<float2*>(&C[(size_t)(row + 8) * CH + col]);
            *p0 = make_float2(acc[mf][nf][0], acc[mf][nf][1]);
            *p1 = make_float2(acc[mf][nf][2], acc[mf][nf][3]);
        }
    }
}

// ---------------------------------------------------------------------------
// Launch
// ---------------------------------------------------------------------------
extern "C" void kernel_launch(void* const* d_in, const int* in_sizes, int n_in,
                              void* d_out, int out_size) {
    (void)in_sizes; (void)n_in; (void)out_size;
    const float* x   = (const float*)d_in[0];
    const float* bw1 = (const float*)d_in[1];
    const float* sw1 = (const float*)d_in[2];
    const float* bw2 = (const float*)d_in[3];
    const float* sw2 = (const float*)d_in[4];
    float* out = (float*)d_out;

    cudaFuncSetAttribute(kan_gemm_kernel,
                         cudaFuncAttributeMaxDynamicSharedMemorySize, SMEM_TOTAL);

    const int packBlocks = (CH * KTOT + 255) / 256;
    pack_w_kernel<<<packBlocks, 256>>>(bw1, sw1, 0);
    pack_w_kernel<<<packBlocks, 256>>>(bw2, sw2, 1);

    dim3 basGrid(CH / 256, N_TOK);
    dim3 gemmGrid(CH / BN, N_TOK / BM);   // (8, 64)

    basis_kernel<<<basGrid, 256>>>(x, 0);
    kan_gemm_kernel<<<gemmGrid, 256, SMEM_TOTAL>>>(0, out);
    basis_kernel<<<basGrid, 256>>>(x, 1);
    kan_gemm_kernel<<<gemmGrid, 256, SMEM_TOTAL>>>(1, out);
}